// round 2
// baseline (speedup 1.0000x reference)
#include <cuda_runtime.h>
#include <math.h>

#define NB 2
#define NT 2048
#define ND 2048
#define NH 16
#define HDIM 128
#define HALF 64
#define SCALE 0.02209708691207961f   // 1/sqrt(2048)

// ---- scratch (device globals: allocation-free) ----
__device__ float g_q[NB * NH * NT * HDIM];
__device__ float g_k[NB * NH * NT * HDIM];
__device__ float g_v[NB * NH * NT * HDIM];
__device__ float g_attn[NB * NT * ND];

// ============================================================
// Shared SGEMM mainloop: C = A(M,K) @ W(N,K)^T
// BM=BN=128, BK=32, 256 threads, 8x8 microtile per thread.
// Smem k-major with stride 132 (pad 128->132 cuts STS conflicts 8-way -> 4-way
// while keeping all LDS.128 reads 16B-aligned).
// ============================================================
#define GS 132

__device__ __forceinline__ void gemm_mainloop(
    const float* __restrict__ A, const float* __restrict__ W,
    int K, int row0, int col0,
    float acc[8][8], float As[32][GS], float Bs[32][GS], int tid)
{
    const int tx = tid & 15, ty = tid >> 4;
    for (int k0 = 0; k0 < K; k0 += 32) {
        #pragma unroll
        for (int i = 0; i < 4; i++) {
            int idx = tid + i * 256;
            int m  = idx >> 3;
            int kq = (idx & 7) << 2;
            float4 va = *(const float4*)(A + (size_t)(row0 + m) * K + k0 + kq);
            As[kq + 0][m] = va.x; As[kq + 1][m] = va.y;
            As[kq + 2][m] = va.z; As[kq + 3][m] = va.w;
            float4 vb = *(const float4*)(W + (size_t)(col0 + m) * K + k0 + kq);
            Bs[kq + 0][m] = vb.x; Bs[kq + 1][m] = vb.y;
            Bs[kq + 2][m] = vb.z; Bs[kq + 3][m] = vb.w;
        }
        __syncthreads();
        #pragma unroll
        for (int kk = 0; kk < 32; kk++) {
            float a[8], b[8];
            *(float4*)&a[0] = *(const float4*)&As[kk][ty * 8];
            *(float4*)&a[4] = *(const float4*)&As[kk][ty * 8 + 4];
            *(float4*)&b[0] = *(const float4*)&Bs[kk][tx * 8];
            *(float4*)&b[4] = *(const float4*)&Bs[kk][tx * 8 + 4];
            #pragma unroll
            for (int i2 = 0; i2 < 8; i2++)
                #pragma unroll
                for (int j2 = 0; j2 < 8; j2++)
                    acc[i2][j2] += a[i2] * b[j2];
        }
        __syncthreads();
    }
}

// ============================================================
// QKV GEMM: qkv = x @ w_qkv^T + b_qkv, scatter to q/k/v [B,H,T,hd]
// ============================================================
__global__ __launch_bounds__(256) void qkv_gemm_kernel(
    const float* __restrict__ x, const float* __restrict__ w,
    const float* __restrict__ bias)
{
    __shared__ float As[32][GS];
    __shared__ float Bs[32][GS];
    float acc[8][8] = {};
    const int tid = threadIdx.x;
    const int row0 = blockIdx.y * 128;
    const int col0 = blockIdx.x * 128;
    gemm_mainloop(x, w, ND, row0, col0, acc, As, Bs, tid);

    const int tx = tid & 15, ty = tid >> 4;
    // col block of 128 is fully inside one (head, which) 128-segment
    const int cbase = col0 + tx * 8;
    const int h     = cbase / 384;
    const int rem   = cbase % 384;
    const int which = rem / 128;
    const int dbase = rem - which * 128;
    float* dst = (which == 0) ? g_q : ((which == 1) ? g_k : g_v);
    float bv[8];
    #pragma unroll
    for (int j = 0; j < 8; j++) bv[j] = bias[cbase + j];

    #pragma unroll
    for (int i = 0; i < 8; i++) {
        int rr = row0 + ty * 8 + i;
        int b_ = rr >> 11;        // / 2048
        int t_ = rr & 2047;
        float* p = dst + ((size_t)(b_ * NH + h) * NT + t_) * HDIM + dbase;
        float4 v0, v1;
        v0.x = acc[i][0] + bv[0]; v0.y = acc[i][1] + bv[1];
        v0.z = acc[i][2] + bv[2]; v0.w = acc[i][3] + bv[3];
        v1.x = acc[i][4] + bv[4]; v1.y = acc[i][5] + bv[5];
        v1.z = acc[i][6] + bv[6]; v1.w = acc[i][7] + bv[7];
        *(float4*)p = v0;
        *(float4*)(p + 4) = v1;
    }
}

// ============================================================
// Output proj: out = g_attn @ w_out^T + b_out
// ============================================================
__global__ __launch_bounds__(256) void proj_gemm_kernel(
    const float* __restrict__ w, const float* __restrict__ bias,
    float* __restrict__ out)
{
    __shared__ float As[32][GS];
    __shared__ float Bs[32][GS];
    float acc[8][8] = {};
    const int tid = threadIdx.x;
    const int row0 = blockIdx.y * 128;
    const int col0 = blockIdx.x * 128;
    gemm_mainloop(g_attn, w, ND, row0, col0, acc, As, Bs, tid);

    const int tx = tid & 15, ty = tid >> 4;
    const int cbase = col0 + tx * 8;
    float bv[8];
    #pragma unroll
    for (int j = 0; j < 8; j++) bv[j] = bias[cbase + j];

    #pragma unroll
    for (int i = 0; i < 8; i++) {
        int rr = row0 + ty * 8 + i;
        float* p = out + (size_t)rr * ND + cbase;
        float4 v0, v1;
        v0.x = acc[i][0] + bv[0]; v0.y = acc[i][1] + bv[1];
        v0.z = acc[i][2] + bv[2]; v0.w = acc[i][3] + bv[3];
        v1.x = acc[i][4] + bv[4]; v1.y = acc[i][5] + bv[5];
        v1.z = acc[i][6] + bv[6]; v1.w = acc[i][7] + bv[7];
        *(float4*)p = v0;
        *(float4*)(p + 4) = v1;
    }
}

// ============================================================
// RoPE in-place on g_q, g_k
// ============================================================
__global__ __launch_bounds__(256) void rope_kernel()
{
    int idx = blockIdx.x * 256 + threadIdx.x;  // < NB*NH*NT*HALF
    int d  = idx & 63;
    int t  = (idx >> 6) & 2047;
    int bh = idx >> 17;
    float inv = powf(10000.0f, -(float)d * (1.0f / 64.0f));
    float ang = (float)t * inv;
    float s, c;
    sincosf(ang, &s, &c);
    size_t base = ((size_t)bh * NT + t) * HDIM;

    float q1 = g_q[base + d], q2 = g_q[base + d + HALF];
    g_q[base + d]        = q1 * c - q2 * s;
    g_q[base + d + HALF] = q1 * s + q2 * c;

    float k1 = g_k[base + d], k2 = g_k[base + d + HALF];
    g_k[base + d]        = k1 * c - k2 * s;
    g_k[base + d + HALF] = k1 * s + k2 * c;
}

// ============================================================
// Causal flash attention, fp32.
// BM = BN = 64, hd = 128, 256 threads (16x16 thread grid).
// Q/K stored d-major [128][68] in smem (conflict-free), V [64][132].
// Each thread: S microtile 4x4 (rows ty*4, cols tx*4),
//              O microtile 4x8 (rows ty*4, cols tx*8).
// ============================================================
#define QK_STR 68
#define V_STR 132
#define FLASH_SMEM ((2 * 128 * QK_STR + 64 * V_STR + 64 * QK_STR) * 4)

__global__ __launch_bounds__(256) void flash_kernel()
{
    extern __shared__ float sm[];
    float (*Qs)[QK_STR] = (float (*)[QK_STR])sm;
    float (*Ks)[QK_STR] = (float (*)[QK_STR])(sm + 128 * QK_STR);
    float (*Vs)[V_STR]  = (float (*)[V_STR])(sm + 2 * 128 * QK_STR);
    float (*Ps)[QK_STR] = (float (*)[QK_STR])(sm + 2 * 128 * QK_STR + 64 * V_STR);

    const int tid = threadIdx.x;
    const int tx = tid & 15, ty = tid >> 4;
    const int qb = (int)gridDim.x - 1 - (int)blockIdx.x;  // heavy blocks first
    const int bh = blockIdx.y;

    // --- load Q tile transposed (d-major): coalesced LDG, cf STS.128 ---
    const float* qg = g_q + ((size_t)bh * NT + qb * 64) * HDIM;
    #pragma unroll
    for (int i = 0; i < 8; i++) {
        int e = tid + i * 256;
        int d  = e & 127;
        int r4 = (e >> 7) << 2;
        float4 v;
        v.x = qg[(r4 + 0) * HDIM + d];
        v.y = qg[(r4 + 1) * HDIM + d];
        v.z = qg[(r4 + 2) * HDIM + d];
        v.w = qg[(r4 + 3) * HDIM + d];
        *(float4*)&Qs[d][r4] = v;
    }

    float m_[4], l_[4], o[4][8];
    #pragma unroll
    for (int i = 0; i < 4; i++) {
        m_[i] = -INFINITY;
        l_[i] = 0.0f;
        #pragma unroll
        for (int c = 0; c < 8; c++) o[i][c] = 0.0f;
    }

    for (int jb = 0; jb <= qb; jb++) {
        __syncthreads();  // protect Ks/Vs/Ps from previous iteration readers
        const float* kg = g_k + ((size_t)bh * NT + jb * 64) * HDIM;
        const float* vg = g_v + ((size_t)bh * NT + jb * 64) * HDIM;
        #pragma unroll
        for (int i = 0; i < 8; i++) {
            int e = tid + i * 256;
            int d  = e & 127;
            int r4 = (e >> 7) << 2;
            float4 v;
            v.x = kg[(r4 + 0) * HDIM + d];
            v.y = kg[(r4 + 1) * HDIM + d];
            v.z = kg[(r4 + 2) * HDIM + d];
            v.w = kg[(r4 + 3) * HDIM + d];
            *(float4*)&Ks[d][r4] = v;
        }
        #pragma unroll
        for (int i = 0; i < 8; i++) {
            int e = tid + i * 256;
            int row = e >> 5;
            int dq  = (e & 31) << 2;
            *(float4*)&Vs[row][dq] = *(const float4*)&vg[row * HDIM + dq];
        }
        __syncthreads();

        // --- S = Q K^T (4x4 per thread) ---
        float s[4][4] = {};
        #pragma unroll 8
        for (int kk = 0; kk < 128; kk++) {
            float a[4], b[4];
            *(float4*)a = *(const float4*)&Qs[kk][ty * 4];
            *(float4*)b = *(const float4*)&Ks[kk][tx * 4];
            #pragma unroll
            for (int i = 0; i < 4; i++)
                #pragma unroll
                for (int jj = 0; jj < 4; jj++)
                    s[i][jj] += a[i] * b[jj];
        }

        // scale + causal mask (only diagonal block needs masking)
        #pragma unroll
        for (int i = 0; i < 4; i++)
            #pragma unroll
            for (int jj = 0; jj < 4; jj++) {
                float v = s[i][jj] * SCALE;
                if (jb == qb && (tx * 4 + jj) > (ty * 4 + i)) v = -1e9f;
                s[i][jj] = v;
            }

        // --- online softmax (row groups: 16 tx lanes per row) ---
        #pragma unroll
        for (int i = 0; i < 4; i++) {
            float mx = fmaxf(fmaxf(s[i][0], s[i][1]), fmaxf(s[i][2], s[i][3]));
            mx = fmaxf(mx, __shfl_xor_sync(0xffffffffu, mx, 8, 16));
            mx = fmaxf(mx, __shfl_xor_sync(0xffffffffu, mx, 4, 16));
            mx = fmaxf(mx, __shfl_xor_sync(0xffffffffu, mx, 2, 16));
            mx = fmaxf(mx, __shfl_xor_sync(0xffffffffu, mx, 1, 16));
            float mn = fmaxf(m_[i], mx);
            float alpha = __expf(m_[i] - mn);
            float rs = 0.0f;
            #pragma unroll
            for (int jj = 0; jj < 4; jj++) {
                float p = __expf(s[i][jj] - mn);
                s[i][jj] = p;
                rs += p;
            }
            rs += __shfl_xor_sync(0xffffffffu, rs, 8, 16);
            rs += __shfl_xor_sync(0xffffffffu, rs, 4, 16);
            rs += __shfl_xor_sync(0xffffffffu, rs, 2, 16);
            rs += __shfl_xor_sync(0xffffffffu, rs, 1, 16);
            l_[i] = l_[i] * alpha + rs;
            m_[i] = mn;
            #pragma unroll
            for (int c = 0; c < 8; c++) o[i][c] *= alpha;
        }

        // stash P
        #pragma unroll
        for (int i = 0; i < 4; i++) {
            float4 pv = make_float4(s[i][0], s[i][1], s[i][2], s[i][3]);
            *(float4*)&Ps[ty * 4 + i][tx * 4] = pv;
        }
        __syncthreads();

        // --- O += P V (4x8 per thread) ---
        #pragma unroll 8
        for (int kk = 0; kk < 64; kk++) {
            float4 va = *(const float4*)&Vs[kk][tx * 8];
            float4 vb = *(const float4*)&Vs[kk][tx * 8 + 4];
            #pragma unroll
            for (int i = 0; i < 4; i++) {
                float p = Ps[ty * 4 + i][kk];
                o[i][0] += p * va.x; o[i][1] += p * va.y;
                o[i][2] += p * va.z; o[i][3] += p * va.w;
                o[i][4] += p * vb.x; o[i][5] += p * vb.y;
                o[i][6] += p * vb.z; o[i][7] += p * vb.w;
            }
        }
    }

    // --- epilogue: normalize + write to g_attn [B,T,D] (D = h*hd + d) ---
    const int b_ = bh >> 4, h = bh & 15;
    #pragma unroll
    for (int i = 0; i < 4; i++) {
        float inv = 1.0f / l_[i];
        int row = qb * 64 + ty * 4 + i;
        float* op = g_attn + ((size_t)(b_ * NT + row)) * ND + h * HDIM + tx * 8;
        float4 v0 = make_float4(o[i][0] * inv, o[i][1] * inv, o[i][2] * inv, o[i][3] * inv);
        float4 v1 = make_float4(o[i][4] * inv, o[i][5] * inv, o[i][6] * inv, o[i][7] * inv);
        *(float4*)op = v0;
        *(float4*)(op + 4) = v1;
    }
}

// ============================================================
extern "C" void kernel_launch(void* const* d_in, const int* in_sizes, int n_in,
                              void* d_out, int out_size)
{
    (void)in_sizes; (void)n_in; (void)out_size;
    const float* x     = (const float*)d_in[0];
    const float* w_qkv = (const float*)d_in[1];
    const float* b_qkv = (const float*)d_in[2];
    const float* w_out = (const float*)d_in[3];
    const float* b_out = (const float*)d_in[4];
    float* out = (float*)d_out;

    qkv_gemm_kernel<<<dim3(48, 32), 256>>>(x, w_qkv, b_qkv);
    rope_kernel<<<(NB * NH * NT * HALF) / 256, 256>>>();
    cudaFuncSetAttribute(flash_kernel,
                         cudaFuncAttributeMaxDynamicSharedMemorySize, FLASH_SMEM);
    flash_kernel<<<dim3(32, 32), 256, FLASH_SMEM>>>();
    proj_gemm_kernel<<<dim3(16, 32), 256>>>(w_out, b_out, out);
}

// round 7
// speedup vs baseline: 1.0103x; 1.0103x over previous
#include <cuda_runtime.h>
#include <cuda_bf16.h>
#include <math.h>
#include <stdint.h>

#define NB 2
#define NT 2048
#define ND 2048
#define NH 16
#define HDIM 128
#define HALF 64
#define SCALE 0.02209708691207961f   // 1/sqrt(2048)
#define KP 6144                       // split-K': 3 * 2048

// ---- scratch (device globals: allocation-free) ----
__device__ float g_q[NB * NH * NT * HDIM];
__device__ float g_k[NB * NH * NT * HDIM];
__device__ float g_v[NB * NH * NT * HDIM];
__device__ float g_attn[NB * NT * ND];
__device__ __nv_bfloat16 g_xp[4096 * KP];       // [A_hi | A_hi | A_lo]
__device__ __nv_bfloat16 g_wqkvp[6144 * KP];    // [B_hi | B_lo | B_hi]
__device__ __nv_bfloat16 g_woutp[2048 * KP];    // [B_hi | B_lo | B_hi]
__device__ __nv_bfloat16 g_attnp[4096 * KP];    // [A_hi | A_hi | A_lo]

// ============================================================
// helpers
// ============================================================
__device__ __forceinline__ uint32_t smem_u32(const void* p) {
    uint32_t a;
    asm("{ .reg .u64 t; cvta.to.shared.u64 t, %1; cvt.u32.u64 %0, t; }" : "=r"(a) : "l"(p));
    return a;
}
#define CP16(dst, src)  asm volatile("cp.async.cg.shared.global [%0], [%1], 16;" :: "r"(dst), "l"(src))
#define CP_COMMIT()     asm volatile("cp.async.commit_group;" ::: "memory")
#define CP_WAIT1()      asm volatile("cp.async.wait_group 1;" ::: "memory")
#define CP_WAIT0()      asm volatile("cp.async.wait_group 0;" ::: "memory")

// m16n8k16 row.col bf16 HMMA, fp32 accum (sm_80+ feature: legal on compute_103)
__device__ __forceinline__ void hmma(float& d0, float& d1, float& d2, float& d3,
                                     uint32_t a0, uint32_t a1, uint32_t a2, uint32_t a3,
                                     uint32_t b0, uint32_t b1)
{
    asm volatile(
        "mma.sync.aligned.m16n8k16.row.col.f32.bf16.bf16.f32 "
        "{%0,%1,%2,%3}, {%4,%5,%6,%7}, {%8,%9}, {%0,%1,%2,%3};"
        : "+f"(d0), "+f"(d1), "+f"(d2), "+f"(d3)
        : "r"(a0), "r"(a1), "r"(a2), "r"(a3), "r"(b0), "r"(b1));
}

// ============================================================
// Split-pack: fp32 row-major [rows x 2048] -> bf16 [rows x 6144]
// slot layout: [0,2048)=hi ; [2048,4096)=lo_slot==1?lo:hi ; [4096,6144)=lo_slot==2?lo:hi
// dsel: 0=g_xp 1=g_wqkvp 2=g_woutp 3=g_attnp (src==nullptr -> g_attn)
// ============================================================
__global__ __launch_bounds__(256) void pack_kernel(const float* __restrict__ src,
                                                   int dsel, int lo_slot)
{
    size_t idx = (size_t)blockIdx.x * 256 + threadIdx.x;   // one float4 group
    size_t r = idx >> 9;               // / 512 groups per row
    int k4 = (int)(idx & 511) << 2;
    const float* s = src ? src : g_attn;
    float4 v = *(const float4*)(s + (r << 11) + k4);

    __nv_bfloat16 h0 = __float2bfloat16(v.x), h1 = __float2bfloat16(v.y);
    __nv_bfloat16 h2 = __float2bfloat16(v.z), h3 = __float2bfloat16(v.w);
    __nv_bfloat16 l0 = __float2bfloat16(v.x - __bfloat162float(h0));
    __nv_bfloat16 l1 = __float2bfloat16(v.y - __bfloat162float(h1));
    __nv_bfloat16 l2 = __float2bfloat16(v.z - __bfloat162float(h2));
    __nv_bfloat16 l3 = __float2bfloat16(v.w - __bfloat162float(h3));

    __nv_bfloat16* dst = (dsel == 0) ? g_xp : (dsel == 1) ? g_wqkvp
                       : (dsel == 2) ? g_woutp : g_attnp;
    __nv_bfloat16* d = dst + r * KP + k4;
    __nv_bfloat162 hi0 = {h0, h1}, hi1 = {h2, h3};
    __nv_bfloat162 lo0 = {l0, l1}, lo1 = {l2, l3};

    ((__nv_bfloat162*)d)[0] = hi0;
    ((__nv_bfloat162*)d)[1] = hi1;
    __nv_bfloat162* d1 = (__nv_bfloat162*)(d + 2048);
    d1[0] = (lo_slot == 1) ? lo0 : hi0;
    d1[1] = (lo_slot == 1) ? lo1 : hi1;
    __nv_bfloat162* d2 = (__nv_bfloat162*)(d + 4096);
    d2[0] = (lo_slot == 2) ? lo0 : hi0;
    d2[1] = (lo_slot == 2) ? lo1 : hi1;
}

// ============================================================
// bf16 HMMA GEMM: C[M,N] = A'[M,KP] @ B'[N,KP]^T (+bias)
// CTA 128x128, BK=32, 256 threads (8 warps, 2x4), warp tile 64x32.
// Smem stride 40 bf16: every 32-bit fragment-load pattern covers all 32 banks
// (word addr = row*20 + t mod 32 is a permutation) -> conflict-free.
// 2-stage cp.async pipeline. fp32 accum in registers.
// WHICH=0: A=g_xp B=g_wqkvp, scatter into g_q/g_k/g_v (+b_qkv)
// WHICH=1: A=g_attnp B=g_woutp, write outp (+b_out)
// ============================================================
#define BK 32
#define AST 40
#define NCH (KP / BK)   // 192

template <int WHICH>
__global__ __launch_bounds__(256, 2) void mma_gemm_kernel(
    const float* __restrict__ bias, float* __restrict__ outp)
{
    __shared__ __nv_bfloat16 As[2][128][AST];
    __shared__ __nv_bfloat16 Bs[2][128][AST];

    const int tid = threadIdx.x;
    const int lane = tid & 31, wid = tid >> 5;
    const int wm = wid >> 2, wn = wid & 3;       // 2 x 4 warp grid
    const int g = lane >> 2, t = lane & 3;       // quad layout
    const int row0 = blockIdx.y * 128;
    const int col0 = blockIdx.x * 128;
    const __nv_bfloat16* A = (WHICH == 0) ? g_xp : g_attnp;
    const __nv_bfloat16* B = (WHICH == 0) ? g_wqkvp : g_woutp;

    const uint32_t sA = smem_u32(As);
    const uint32_t sB = smem_u32(Bs);
    const __nv_bfloat16* Agp = A + (size_t)row0 * KP;
    const __nv_bfloat16* Bgp = B + (size_t)col0 * KP;

    auto load_chunk = [&](int c) {
        const int s = c & 1;
        const __nv_bfloat16* Ab = Agp + c * BK;
        const __nv_bfloat16* Bb = Bgp + c * BK;
        #pragma unroll
        for (int i = 0; i < 2; i++) {
            int idx = tid + i * 256;        // 512 granules: 128 rows x 4
            int r = idx >> 2, gg = idx & 3;
            uint32_t doff = (uint32_t)((s * 128 + r) * AST + gg * 8) * 2;
            CP16(sA + doff, Ab + (size_t)r * KP + gg * 8);
            CP16(sB + doff, Bb + (size_t)r * KP + gg * 8);
        }
        CP_COMMIT();
    };

    float acc[4][4][4];
    #pragma unroll
    for (int mt = 0; mt < 4; mt++)
        #pragma unroll
        for (int nt = 0; nt < 4; nt++)
            #pragma unroll
            for (int j = 0; j < 4; j++) acc[mt][nt][j] = 0.0f;

    load_chunk(0);
    load_chunk(1);

    for (int c = 0; c < NCH; c++) {
        const int s = c & 1;
        // pending groups here: {c, c+1} normally; only {c} at the tail
        if (c + 1 < NCH) CP_WAIT1(); else CP_WAIT0();
        __syncthreads();

        #pragma unroll
        for (int kk = 0; kk < 2; kk++) {     // two k16 steps per BK=32
            uint32_t a[4][4], b[4][2];
            #pragma unroll
            for (int mt = 0; mt < 4; mt++) {
                const uint32_t* r0p = (const uint32_t*)&As[s][wm * 64 + mt * 16 + g][0];
                const uint32_t* r1p = (const uint32_t*)&As[s][wm * 64 + mt * 16 + g + 8][0];
                a[mt][0] = r0p[kk * 8 + t];
                a[mt][1] = r1p[kk * 8 + t];
                a[mt][2] = r0p[kk * 8 + t + 4];
                a[mt][3] = r1p[kk * 8 + t + 4];
            }
            #pragma unroll
            for (int nt = 0; nt < 4; nt++) {
                const uint32_t* bp = (const uint32_t*)&Bs[s][wn * 32 + nt * 8 + g][0];
                b[nt][0] = bp[kk * 8 + t];
                b[nt][1] = bp[kk * 8 + t + 4];
            }
            #pragma unroll
            for (int mt = 0; mt < 4; mt++)
                #pragma unroll
                for (int nt = 0; nt < 4; nt++)
                    hmma(acc[mt][nt][0], acc[mt][nt][1], acc[mt][nt][2], acc[mt][nt][3],
                         a[mt][0], a[mt][1], a[mt][2], a[mt][3],
                         b[nt][0], b[nt][1]);
        }
        __syncthreads();
        if (c + 2 < NCH) load_chunk(c + 2);
    }

    // ---- epilogue: regs (+bias) -> global ----
    const int rbase = row0 + wm * 64;
    #pragma unroll
    for (int mt = 0; mt < 4; mt++) {
        #pragma unroll
        for (int nt = 0; nt < 4; nt++) {
            const int nglob = col0 + wn * 32 + nt * 8;
            const int nc = nglob + t * 2;
            const float b0v = bias[nc], b1v = bias[nc + 1];
            const int r0 = rbase + mt * 16 + g, r1 = r0 + 8;
            float *p0, *p1;
            if (WHICH == 0) {
                int h = nglob / 384;
                int rem = nglob - h * 384;
                int wh = rem >> 7;
                int d0 = (rem & 127) + t * 2;
                float* dst = (wh == 0) ? g_q : (wh == 1) ? g_k : g_v;
                int b_ = r0 >> 11, t_ = r0 & 2047;
                p0 = dst + ((size_t)(b_ * NH + h) * NT + t_) * HDIM + d0;
                b_ = r1 >> 11; t_ = r1 & 2047;
                p1 = dst + ((size_t)(b_ * NH + h) * NT + t_) * HDIM + d0;
            } else {
                p0 = outp + (size_t)r0 * ND + nc;
                p1 = outp + (size_t)r1 * ND + nc;
            }
            float2 v0 = {acc[mt][nt][0] + b0v, acc[mt][nt][1] + b1v};
            float2 v1 = {acc[mt][nt][2] + b0v, acc[mt][nt][3] + b1v};
            *(float2*)p0 = v0;
            *(float2*)p1 = v1;
        }
    }
}

// ============================================================
// RoPE in-place on g_q, g_k
// ============================================================
__global__ __launch_bounds__(256) void rope_kernel()
{
    int idx = blockIdx.x * 256 + threadIdx.x;  // < NB*NH*NT*HALF
    int d  = idx & 63;
    int t  = (idx >> 6) & 2047;
    int bh = idx >> 17;
    float inv = powf(10000.0f, -(float)d * (1.0f / 64.0f));
    float ang = (float)t * inv;
    float s, c;
    sincosf(ang, &s, &c);
    size_t base = ((size_t)bh * NT + t) * HDIM;

    float q1 = g_q[base + d], q2 = g_q[base + d + HALF];
    g_q[base + d]        = q1 * c - q2 * s;
    g_q[base + d + HALF] = q1 * s + q2 * c;

    float k1 = g_k[base + d], k2 = g_k[base + d + HALF];
    g_k[base + d]        = k1 * c - k2 * s;
    g_k[base + d + HALF] = k1 * s + k2 * c;
}

// ============================================================
// Causal flash attention, fp32 (unchanged from passing R2 kernel)
// ============================================================
#define QK_STR 68
#define V_STR 132
#define FLASH_SMEM ((2 * 128 * QK_STR + 64 * V_STR + 64 * QK_STR) * 4)

__global__ __launch_bounds__(256) void flash_kernel()
{
    extern __shared__ float sm[];
    float (*Qs)[QK_STR] = (float (*)[QK_STR])sm;
    float (*Ks)[QK_STR] = (float (*)[QK_STR])(sm + 128 * QK_STR);
    float (*Vs)[V_STR]  = (float (*)[V_STR])(sm + 2 * 128 * QK_STR);
    float (*Ps)[QK_STR] = (float (*)[QK_STR])(sm + 2 * 128 * QK_STR + 64 * V_STR);

    const int tid = threadIdx.x;
    const int tx = tid & 15, ty = tid >> 4;
    const int qb = (int)gridDim.x - 1 - (int)blockIdx.x;
    const int bh = blockIdx.y;

    const float* qg = g_q + ((size_t)bh * NT + qb * 64) * HDIM;
    #pragma unroll
    for (int i = 0; i < 8; i++) {
        int e = tid + i * 256;
        int d  = e & 127;
        int r4 = (e >> 7) << 2;
        float4 v;
        v.x = qg[(r4 + 0) * HDIM + d];
        v.y = qg[(r4 + 1) * HDIM + d];
        v.z = qg[(r4 + 2) * HDIM + d];
        v.w = qg[(r4 + 3) * HDIM + d];
        *(float4*)&Qs[d][r4] = v;
    }

    float m_[4], l_[4], o[4][8];
    #pragma unroll
    for (int i = 0; i < 4; i++) {
        m_[i] = -INFINITY;
        l_[i] = 0.0f;
        #pragma unroll
        for (int c = 0; c < 8; c++) o[i][c] = 0.0f;
    }

    for (int jb = 0; jb <= qb; jb++) {
        __syncthreads();
        const float* kg = g_k + ((size_t)bh * NT + jb * 64) * HDIM;
        const float* vg = g_v + ((size_t)bh * NT + jb * 64) * HDIM;
        #pragma unroll
        for (int i = 0; i < 8; i++) {
            int e = tid + i * 256;
            int d  = e & 127;
            int r4 = (e >> 7) << 2;
            float4 v;
            v.x = kg[(r4 + 0) * HDIM + d];
            v.y = kg[(r4 + 1) * HDIM + d];
            v.z = kg[(r4 + 2) * HDIM + d];
            v.w = kg[(r4 + 3) * HDIM + d];
            *(float4*)&Ks[d][r4] = v;
        }
        #pragma unroll
        for (int i = 0; i < 8; i++) {
            int e = tid + i * 256;
            int row = e >> 5;
            int dq  = (e & 31) << 2;
            *(float4*)&Vs[row][dq] = *(const float4*)&vg[row * HDIM + dq];
        }
        __syncthreads();

        float s[4][4] = {};
        #pragma unroll 8
        for (int kk = 0; kk < 128; kk++) {
            float a[4], b[4];
            *(float4*)a = *(const float4*)&Qs[kk][ty * 4];
            *(float4*)b = *(const float4*)&Ks[kk][tx * 4];
            #pragma unroll
            for (int i = 0; i < 4; i++)
                #pragma unroll
                for (int jj = 0; jj < 4; jj++)
                    s[i][jj] += a[i] * b[jj];
        }

        #pragma unroll
        for (int i = 0; i < 4; i++)
            #pragma unroll
            for (int jj = 0; jj < 4; jj++) {
                float v = s[i][jj] * SCALE;
                if (jb == qb && (tx * 4 + jj) > (ty * 4 + i)) v = -1e9f;
                s[i][jj] = v;
            }

        #pragma unroll
        for (int i = 0; i < 4; i++) {
            float mx = fmaxf(fmaxf(s[i][0], s[i][1]), fmaxf(s[i][2], s[i][3]));
            mx = fmaxf(mx, __shfl_xor_sync(0xffffffffu, mx, 8, 16));
            mx = fmaxf(mx, __shfl_xor_sync(0xffffffffu, mx, 4, 16));
            mx = fmaxf(mx, __shfl_xor_sync(0xffffffffu, mx, 2, 16));
            mx = fmaxf(mx, __shfl_xor_sync(0xffffffffu, mx, 1, 16));
            float mn = fmaxf(m_[i], mx);
            float alpha = __expf(m_[i] - mn);
            float rs = 0.0f;
            #pragma unroll
            for (int jj = 0; jj < 4; jj++) {
                float p = __expf(s[i][jj] - mn);
                s[i][jj] = p;
                rs += p;
            }
            rs += __shfl_xor_sync(0xffffffffu, rs, 8, 16);
            rs += __shfl_xor_sync(0xffffffffu, rs, 4, 16);
            rs += __shfl_xor_sync(0xffffffffu, rs, 2, 16);
            rs += __shfl_xor_sync(0xffffffffu, rs, 1, 16);
            l_[i] = l_[i] * alpha + rs;
            m_[i] = mn;
            #pragma unroll
            for (int c = 0; c < 8; c++) o[i][c] *= alpha;
        }

        #pragma unroll
        for (int i = 0; i < 4; i++) {
            float4 pv = make_float4(s[i][0], s[i][1], s[i][2], s[i][3]);
            *(float4*)&Ps[ty * 4 + i][tx * 4] = pv;
        }
        __syncthreads();

        #pragma unroll 8
        for (int kk = 0; kk < 64; kk++) {
            float4 va = *(const float4*)&Vs[kk][tx * 8];
            float4 vb = *(const float4*)&Vs[kk][tx * 8 + 4];
            #pragma unroll
            for (int i = 0; i < 4; i++) {
                float p = Ps[ty * 4 + i][kk];
                o[i][0] += p * va.x; o[i][1] += p * va.y;
                o[i][2] += p * va.z; o[i][3] += p * va.w;
                o[i][4] += p * vb.x; o[i][5] += p * vb.y;
                o[i][6] += p * vb.z; o[i][7] += p * vb.w;
            }
        }
    }

    const int b_ = bh >> 4, h = bh & 15;
    #pragma unroll
    for (int i = 0; i < 4; i++) {
        float inv = 1.0f / l_[i];
        int row = qb * 64 + ty * 4 + i;
        float* op = g_attn + ((size_t)(b_ * NT + row)) * ND + h * HDIM + tx * 8;
        float4 v0 = make_float4(o[i][0] * inv, o[i][1] * inv, o[i][2] * inv, o[i][3] * inv);
        float4 v1 = make_float4(o[i][4] * inv, o[i][5] * inv, o[i][6] * inv, o[i][7] * inv);
        *(float4*)op = v0;
        *(float4*)(op + 4) = v1;
    }
}

// ============================================================
extern "C" void kernel_launch(void* const* d_in, const int* in_sizes, int n_in,
                              void* d_out, int out_size)
{
    (void)in_sizes; (void)n_in; (void)out_size;
    const float* x     = (const float*)d_in[0];
    const float* w_qkv = (const float*)d_in[1];
    const float* b_qkv = (const float*)d_in[2];
    const float* w_out = (const float*)d_in[3];
    const float* b_out = (const float*)d_in[4];
    float* out = (float*)d_out;

    cudaFuncSetAttribute(flash_kernel,
                         cudaFuncAttributeMaxDynamicSharedMemorySize, FLASH_SMEM);

    // pack inputs to bf16 hi/lo split
    pack_kernel<<<8192, 256>>>(x, 0, 2);        // g_xp    [hi|hi|lo]
    pack_kernel<<<12288, 256>>>(w_qkv, 1, 1);   // g_wqkvp [hi|lo|hi]
    pack_kernel<<<4096, 256>>>(w_out, 2, 1);    // g_woutp [hi|lo|hi]

    // QKV projection on tensor cores (M=4096, N=6144)
    mma_gemm_kernel<0><<<dim3(48, 32), 256>>>(b_qkv, nullptr);

    rope_kernel<<<(NB * NH * NT * HALF) / 256, 256>>>();
    flash_kernel<<<dim3(32, 32), 256, FLASH_SMEM>>>();

    // pack attention output, then out-projection (M=4096, N=2048)
    pack_kernel<<<8192, 256>>>(nullptr, 3, 2);  // g_attnp [hi|hi|lo]
    mma_gemm_kernel<1><<<dim3(16, 32), 256>>>(b_out, out);
}

// round 9
// speedup vs baseline: 1.9307x; 1.9110x over previous
#include <cuda_runtime.h>
#include <cuda.h>
#include <cuda_bf16.h>
#include <math.h>
#include <stdint.h>

#define NB 2
#define NT 2048
#define ND 2048
#define NH 16
#define HDIM 128
#define HALF 64
#define SCALE 0.02209708691207961f   // 1/sqrt(2048)
#define KP 6144                       // split-K': 3 * 2048

// ---- scratch (device globals: allocation-free) ----
__device__ float g_q[NB * NH * NT * HDIM];
__device__ float g_k[NB * NH * NT * HDIM];
__device__ float g_v[NB * NH * NT * HDIM];
__device__ float g_attn[NB * NT * ND];
__device__ __nv_bfloat16 g_xp[4096 * KP];       // [A_hi | A_hi | A_lo]
__device__ __nv_bfloat16 g_wqkvp[6144 * KP];    // [B_hi | B_lo | B_hi]
__device__ __nv_bfloat16 g_woutp[2048 * KP];    // [B_hi | B_lo | B_hi]
__device__ __nv_bfloat16 g_attnp[4096 * KP];    // [A_hi | A_hi | A_lo]

// ============================================================
// helpers
// ============================================================
__device__ __forceinline__ uint32_t smem_u32(const void* p) {
    uint32_t a;
    asm("{ .reg .u64 t; cvta.to.shared.u64 t, %1; cvt.u32.u64 %0, t; }" : "=r"(a) : "l"(p));
    return a;
}
#define MBAR_INIT(mb, c) asm volatile("mbarrier.init.shared.b64 [%0], %1;" :: "r"(mb), "r"(c) : "memory")
#define MBAR_EXPECT(mb, bytes) asm volatile("mbarrier.arrive.expect_tx.shared.b64 _, [%0], %1;" :: "r"(mb), "r"(bytes) : "memory")
#define MBAR_WAIT(mb, par) do {                                                             \
    asm volatile("{\n\t.reg .pred P1;\n\tWAIT_%=:\n\t"                                      \
        "mbarrier.try_wait.parity.acquire.cta.shared::cta.b64 P1, [%0], %1, 0x989680;\n\t"  \
        "@P1 bra.uni DONE_%=;\n\tbra.uni WAIT_%=;\n\tDONE_%=:\n\t}"                         \
        :: "r"(mb), "r"(par) : "memory");                                                    \
} while (0)
#define TMA2D(dst, map, cx, cy, mb)                                                          \
    asm volatile("cp.async.bulk.tensor.2d.shared::cta.global.tile.mbarrier::complete_tx::bytes " \
        "[%0], [%1, {%2, %3}], [%4];"                                                        \
        :: "r"(dst), "l"(map), "r"(cx), "r"(cy), "r"(mb) : "memory")

// m16n8k16 row.col bf16 HMMA, fp32 accum (sm_80+ feature: legal on compute_103)
__device__ __forceinline__ void hmma(float& d0, float& d1, float& d2, float& d3,
                                     uint32_t a0, uint32_t a1, uint32_t a2, uint32_t a3,
                                     uint32_t b0, uint32_t b1)
{
    asm volatile(
        "mma.sync.aligned.m16n8k16.row.col.f32.bf16.bf16.f32 "
        "{%0,%1,%2,%3}, {%4,%5,%6,%7}, {%8,%9}, {%0,%1,%2,%3};"
        : "+f"(d0), "+f"(d1), "+f"(d2), "+f"(d3)
        : "r"(a0), "r"(a1), "r"(a2), "r"(a3), "r"(b0), "r"(b1));
}

// ============================================================
// Split-pack: fp32 row-major [rows x 2048] -> bf16 [rows x 6144]
// ============================================================
__global__ __launch_bounds__(256) void pack_kernel(const float* __restrict__ src,
                                                   int dsel, int lo_slot)
{
    size_t idx = (size_t)blockIdx.x * 256 + threadIdx.x;   // one float4 group
    size_t r = idx >> 9;               // / 512 groups per row
    int k4 = (int)(idx & 511) << 2;
    const float* s = src ? src : g_attn;
    float4 v = *(const float4*)(s + (r << 11) + k4);

    __nv_bfloat16 h0 = __float2bfloat16(v.x), h1 = __float2bfloat16(v.y);
    __nv_bfloat16 h2 = __float2bfloat16(v.z), h3 = __float2bfloat16(v.w);
    __nv_bfloat16 l0 = __float2bfloat16(v.x - __bfloat162float(h0));
    __nv_bfloat16 l1 = __float2bfloat16(v.y - __bfloat162float(h1));
    __nv_bfloat16 l2 = __float2bfloat16(v.z - __bfloat162float(h2));
    __nv_bfloat16 l3 = __float2bfloat16(v.w - __bfloat162float(h3));

    __nv_bfloat16* dst = (dsel == 0) ? g_xp : (dsel == 1) ? g_wqkvp
                       : (dsel == 2) ? g_woutp : g_attnp;
    __nv_bfloat16* d = dst + r * KP + k4;
    __nv_bfloat162 hi0 = {h0, h1}, hi1 = {h2, h3};
    __nv_bfloat162 lo0 = {l0, l1}, lo1 = {l2, l3};

    ((__nv_bfloat162*)d)[0] = hi0;
    ((__nv_bfloat162*)d)[1] = hi1;
    __nv_bfloat162* d1 = (__nv_bfloat162*)(d + 2048);
    d1[0] = (lo_slot == 1) ? lo0 : hi0;
    d1[1] = (lo_slot == 1) ? lo1 : hi1;
    __nv_bfloat162* d2 = (__nv_bfloat162*)(d + 4096);
    d2[0] = (lo_slot == 2) ? lo0 : hi0;
    d2[1] = (lo_slot == 2) ? lo1 : hi1;
}

// ============================================================
// bf16 HMMA GEMM with TMA loads: C[M,N] = A'[M,KP] @ B'[N,KP]^T (+bias)
// CTA 128x128, BK=64, 3-stage TMA pipeline (SW128 tiles, 16KB each),
// 256 threads (8 warps 2x4), warp tile 64x32, fp32 accum in regs.
// Fragment LDS under SW128: phys = off ^ ((row&7)<<4); per-instruction
// bank = (kk*8+t) ^ ((g&7)<<2) -> all 32 banks, conflict-free.
// ============================================================
#define BK 64
#define NCH (KP / BK)          // 96
#define STG_BYTES 16384        // 128 rows x 128B
#define GEMM_DSMEM (1024 + 3 * 2 * STG_BYTES + 64)

template <int WHICH>
__global__ __launch_bounds__(256, 2) void mma_gemm_kernel(
    const __grid_constant__ CUtensorMap tmA,
    const __grid_constant__ CUtensorMap tmB,
    const float* __restrict__ bias, float* __restrict__ outp)
{
    extern __shared__ char smem[];
    const uint32_t sb_raw = smem_u32(smem);
    const uint32_t sb0 = (sb_raw + 1023u) & ~1023u;      // 1024-aligned for SW128
    char* base = smem + (sb0 - sb_raw);
    const uint32_t mb0 = sb0 + 3 * 2 * STG_BYTES;        // 3 mbarriers after stages

    const int tid = threadIdx.x;
    const int lane = tid & 31, wid = tid >> 5;
    const int wm = wid >> 2, wn = wid & 3;               // 2 x 4 warp grid
    const int g = lane >> 2, t = lane & 3;               // quad layout
    const int row0 = blockIdx.y * 128;
    const int col0 = blockIdx.x * 128;

    if (tid == 0) {
        MBAR_INIT(mb0 + 0, 1);
        MBAR_INIT(mb0 + 8, 1);
        MBAR_INIT(mb0 + 16, 1);
    }
    __syncthreads();

    auto issue = [&](int c) {
        const int s = c % 3;
        const uint32_t stA = sb0 + s * 2 * STG_BYTES;
        const uint32_t stB = stA + STG_BYTES;
        const uint32_t mb = mb0 + s * 8;
        MBAR_EXPECT(mb, 2 * STG_BYTES);
        TMA2D(stA, &tmA, c * BK, row0, mb);
        TMA2D(stB, &tmB, c * BK, col0, mb);
    };

    if (tid == 0) { issue(0); issue(1); issue(2); }

    float acc[4][4][4];
    #pragma unroll
    for (int mt = 0; mt < 4; mt++)
        #pragma unroll
        for (int nt = 0; nt < 4; nt++)
            #pragma unroll
            for (int j = 0; j < 4; j++) acc[mt][nt][j] = 0.0f;

    const uint32_t xm = (uint32_t)((g & 7) << 4);        // SW128 XOR mask (const/thread)

    for (int c = 0; c < NCH; c++) {
        const int s = c % 3;
        MBAR_WAIT(mb0 + s * 8, (c / 3) & 1);
        const char* stA = base + s * 2 * STG_BYTES;
        const char* stB = stA + STG_BYTES;

        #pragma unroll
        for (int kk = 0; kk < 4; kk++) {                 // four k16 steps per BK=64
            const uint32_t off0 = (uint32_t)(kk * 32 + t * 4) ^ xm;
            const uint32_t off1 = (uint32_t)(kk * 32 + t * 4 + 16) ^ xm;
            uint32_t a[4][4], b[4][2];
            #pragma unroll
            for (int mt = 0; mt < 4; mt++) {
                const char* r0p = stA + (wm * 64 + mt * 16 + g) * 128;
                const char* r1p = r0p + 8 * 128;
                a[mt][0] = *(const uint32_t*)(r0p + off0);
                a[mt][1] = *(const uint32_t*)(r1p + off0);
                a[mt][2] = *(const uint32_t*)(r0p + off1);
                a[mt][3] = *(const uint32_t*)(r1p + off1);
            }
            #pragma unroll
            for (int nt = 0; nt < 4; nt++) {
                const char* bp = stB + (wn * 32 + nt * 8 + g) * 128;
                b[nt][0] = *(const uint32_t*)(bp + off0);
                b[nt][1] = *(const uint32_t*)(bp + off1);
            }
            #pragma unroll
            for (int mt = 0; mt < 4; mt++)
                #pragma unroll
                for (int nt = 0; nt < 4; nt++)
                    hmma(acc[mt][nt][0], acc[mt][nt][1], acc[mt][nt][2], acc[mt][nt][3],
                         a[mt][0], a[mt][1], a[mt][2], a[mt][3],
                         b[nt][0], b[nt][1]);
        }
        __syncthreads();                                  // stage s fully consumed
        if (tid == 0 && c + 3 < NCH) issue(c + 3);
    }

    // ---- epilogue: regs (+bias) -> global (audited in R5-R7) ----
    const int rbase = row0 + wm * 64;
    #pragma unroll
    for (int mt = 0; mt < 4; mt++) {
        #pragma unroll
        for (int nt = 0; nt < 4; nt++) {
            const int nglob = col0 + wn * 32 + nt * 8;
            const int nc = nglob + t * 2;
            const float b0v = bias[nc], b1v = bias[nc + 1];
            const int r0 = rbase + mt * 16 + g, r1 = r0 + 8;
            float *p0, *p1;
            if (WHICH == 0) {
                int h = nglob / 384;
                int rem = nglob - h * 384;
                int wh = rem >> 7;
                int d0 = (rem & 127) + t * 2;
                float* dst = (wh == 0) ? g_q : (wh == 1) ? g_k : g_v;
                int b_ = r0 >> 11, t_ = r0 & 2047;
                p0 = dst + ((size_t)(b_ * NH + h) * NT + t_) * HDIM + d0;
                b_ = r1 >> 11; t_ = r1 & 2047;
                p1 = dst + ((size_t)(b_ * NH + h) * NT + t_) * HDIM + d0;
            } else {
                p0 = outp + (size_t)r0 * ND + nc;
                p1 = outp + (size_t)r1 * ND + nc;
            }
            float2 v0 = {acc[mt][nt][0] + b0v, acc[mt][nt][1] + b1v};
            float2 v1 = {acc[mt][nt][2] + b0v, acc[mt][nt][3] + b1v};
            *(float2*)p0 = v0;
            *(float2*)p1 = v1;
        }
    }
}

// ============================================================
// RoPE in-place on g_q, g_k
// ============================================================
__global__ __launch_bounds__(256) void rope_kernel()
{
    int idx = blockIdx.x * 256 + threadIdx.x;  // < NB*NH*NT*HALF
    int d  = idx & 63;
    int t  = (idx >> 6) & 2047;
    int bh = idx >> 17;
    float inv = powf(10000.0f, -(float)d * (1.0f / 64.0f));
    float ang = (float)t * inv;
    float s, c;
    sincosf(ang, &s, &c);
    size_t base = ((size_t)bh * NT + t) * HDIM;

    float q1 = g_q[base + d], q2 = g_q[base + d + HALF];
    g_q[base + d]        = q1 * c - q2 * s;
    g_q[base + d + HALF] = q1 * s + q2 * c;

    float k1 = g_k[base + d], k2 = g_k[base + d + HALF];
    g_k[base + d]        = k1 * c - k2 * s;
    g_k[base + d + HALF] = k1 * s + k2 * c;
}

// ============================================================
// Causal flash attention, fp32 (unchanged from passing R2 kernel)
// ============================================================
#define QK_STR 68
#define V_STR 132
#define FLASH_SMEM ((2 * 128 * QK_STR + 64 * V_STR + 64 * QK_STR) * 4)

__global__ __launch_bounds__(256) void flash_kernel()
{
    extern __shared__ float sm[];
    float (*Qs)[QK_STR] = (float (*)[QK_STR])sm;
    float (*Ks)[QK_STR] = (float (*)[QK_STR])(sm + 128 * QK_STR);
    float (*Vs)[V_STR]  = (float (*)[V_STR])(sm + 2 * 128 * QK_STR);
    float (*Ps)[QK_STR] = (float (*)[QK_STR])(sm + 2 * 128 * QK_STR + 64 * V_STR);

    const int tid = threadIdx.x;
    const int tx = tid & 15, ty = tid >> 4;
    const int qb = (int)gridDim.x - 1 - (int)blockIdx.x;
    const int bh = blockIdx.y;

    const float* qg = g_q + ((size_t)bh * NT + qb * 64) * HDIM;
    #pragma unroll
    for (int i = 0; i < 8; i++) {
        int e = tid + i * 256;
        int d  = e & 127;
        int r4 = (e >> 7) << 2;
        float4 v;
        v.x = qg[(r4 + 0) * HDIM + d];
        v.y = qg[(r4 + 1) * HDIM + d];
        v.z = qg[(r4 + 2) * HDIM + d];
        v.w = qg[(r4 + 3) * HDIM + d];
        *(float4*)&Qs[d][r4] = v;
    }

    float m_[4], l_[4], o[4][8];
    #pragma unroll
    for (int i = 0; i < 4; i++) {
        m_[i] = -INFINITY;
        l_[i] = 0.0f;
        #pragma unroll
        for (int c = 0; c < 8; c++) o[i][c] = 0.0f;
    }

    for (int jb = 0; jb <= qb; jb++) {
        __syncthreads();
        const float* kg = g_k + ((size_t)bh * NT + jb * 64) * HDIM;
        const float* vg = g_v + ((size_t)bh * NT + jb * 64) * HDIM;
        #pragma unroll
        for (int i = 0; i < 8; i++) {
            int e = tid + i * 256;
            int d  = e & 127;
            int r4 = (e >> 7) << 2;
            float4 v;
            v.x = kg[(r4 + 0) * HDIM + d];
            v.y = kg[(r4 + 1) * HDIM + d];
            v.z = kg[(r4 + 2) * HDIM + d];
            v.w = kg[(r4 + 3) * HDIM + d];
            *(float4*)&Ks[d][r4] = v;
        }
        #pragma unroll
        for (int i = 0; i < 8; i++) {
            int e = tid + i * 256;
            int row = e >> 5;
            int dq  = (e & 31) << 2;
            *(float4*)&Vs[row][dq] = *(const float4*)&vg[row * HDIM + dq];
        }
        __syncthreads();

        float s[4][4] = {};
        #pragma unroll 8
        for (int kk = 0; kk < 128; kk++) {
            float a[4], b[4];
            *(float4*)a = *(const float4*)&Qs[kk][ty * 4];
            *(float4*)b = *(const float4*)&Ks[kk][tx * 4];
            #pragma unroll
            for (int i = 0; i < 4; i++)
                #pragma unroll
                for (int jj = 0; jj < 4; jj++)
                    s[i][jj] += a[i] * b[jj];
        }

        #pragma unroll
        for (int i = 0; i < 4; i++)
            #pragma unroll
            for (int jj = 0; jj < 4; jj++) {
                float v = s[i][jj] * SCALE;
                if (jb == qb && (tx * 4 + jj) > (ty * 4 + i)) v = -1e9f;
                s[i][jj] = v;
            }

        #pragma unroll
        for (int i = 0; i < 4; i++) {
            float mx = fmaxf(fmaxf(s[i][0], s[i][1]), fmaxf(s[i][2], s[i][3]));
            mx = fmaxf(mx, __shfl_xor_sync(0xffffffffu, mx, 8, 16));
            mx = fmaxf(mx, __shfl_xor_sync(0xffffffffu, mx, 4, 16));
            mx = fmaxf(mx, __shfl_xor_sync(0xffffffffu, mx, 2, 16));
            mx = fmaxf(mx, __shfl_xor_sync(0xffffffffu, mx, 1, 16));
            float mn = fmaxf(m_[i], mx);
            float alpha = __expf(m_[i] - mn);
            float rs = 0.0f;
            #pragma unroll
            for (int jj = 0; jj < 4; jj++) {
                float p = __expf(s[i][jj] - mn);
                s[i][jj] = p;
                rs += p;
            }
            rs += __shfl_xor_sync(0xffffffffu, rs, 8, 16);
            rs += __shfl_xor_sync(0xffffffffu, rs, 4, 16);
            rs += __shfl_xor_sync(0xffffffffu, rs, 2, 16);
            rs += __shfl_xor_sync(0xffffffffu, rs, 1, 16);
            l_[i] = l_[i] * alpha + rs;
            m_[i] = mn;
            #pragma unroll
            for (int c = 0; c < 8; c++) o[i][c] *= alpha;
        }

        #pragma unroll
        for (int i = 0; i < 4; i++) {
            float4 pv = make_float4(s[i][0], s[i][1], s[i][2], s[i][3]);
            *(float4*)&Ps[ty * 4 + i][tx * 4] = pv;
        }
        __syncthreads();

        #pragma unroll 8
        for (int kk = 0; kk < 64; kk++) {
            float4 va = *(const float4*)&Vs[kk][tx * 8];
            float4 vb = *(const float4*)&Vs[kk][tx * 8 + 4];
            #pragma unroll
            for (int i = 0; i < 4; i++) {
                float p = Ps[ty * 4 + i][kk];
                o[i][0] += p * va.x; o[i][1] += p * va.y;
                o[i][2] += p * va.z; o[i][3] += p * va.w;
                o[i][4] += p * vb.x; o[i][5] += p * vb.y;
                o[i][6] += p * vb.z; o[i][7] += p * vb.w;
            }
        }
    }

    const int b_ = bh >> 4, h = bh & 15;
    #pragma unroll
    for (int i = 0; i < 4; i++) {
        float inv = 1.0f / l_[i];
        int row = qb * 64 + ty * 4 + i;
        float* op = g_attn + ((size_t)(b_ * NT + row)) * ND + h * HDIM + tx * 8;
        float4 v0 = make_float4(o[i][0] * inv, o[i][1] * inv, o[i][2] * inv, o[i][3] * inv);
        float4 v1 = make_float4(o[i][4] * inv, o[i][5] * inv, o[i][6] * inv, o[i][7] * inv);
        *(float4*)op = v0;
        *(float4*)(op + 4) = v1;
    }
}

// ============================================================
typedef CUresult (*EncodeFn)(CUtensorMap*, CUtensorMapDataType, cuuint32_t, void*,
                             const cuuint64_t*, const cuuint64_t*, const cuuint32_t*,
                             const cuuint32_t*, CUtensorMapInterleave, CUtensorMapSwizzle,
                             CUtensorMapL2promotion, CUtensorMapFloatOOBfill);

extern "C" void kernel_launch(void* const* d_in, const int* in_sizes, int n_in,
                              void* d_out, int out_size)
{
    (void)in_sizes; (void)n_in; (void)out_size;
    const float* x     = (const float*)d_in[0];
    const float* w_qkv = (const float*)d_in[1];
    const float* b_qkv = (const float*)d_in[2];
    const float* w_out = (const float*)d_in[3];
    const float* b_out = (const float*)d_in[4];
    float* out = (float*)d_out;

    // driver encode fn via runtime API (no -lcuda link dependency)
    void* efp = nullptr;
    cudaDriverEntryPointQueryResult qres;
    cudaGetDriverEntryPoint("cuTensorMapEncodeTiled", &efp, cudaEnableDefault, &qres);
    EncodeFn enc = (EncodeFn)efp;

    void *pxp, *pwq, *pwo, *pat;
    cudaGetSymbolAddress(&pxp, g_xp);
    cudaGetSymbolAddress(&pwq, g_wqkvp);
    cudaGetSymbolAddress(&pwo, g_woutp);
    cudaGetSymbolAddress(&pat, g_attnp);

    auto mkmap = [&](void* basep, unsigned long long rows) {
        CUtensorMap m;
        cuuint64_t dims[2]    = {(cuuint64_t)KP, (cuuint64_t)rows};
        cuuint64_t strides[1] = {(cuuint64_t)KP * 2};
        cuuint32_t box[2]     = {64, 128};
        cuuint32_t es[2]      = {1, 1};
        enc(&m, CU_TENSOR_MAP_DATA_TYPE_BFLOAT16, 2, basep, dims, strides, box, es,
            CU_TENSOR_MAP_INTERLEAVE_NONE, CU_TENSOR_MAP_SWIZZLE_128B,
            CU_TENSOR_MAP_L2_PROMOTION_L2_128B, CU_TENSOR_MAP_FLOAT_OOB_FILL_NONE);
        return m;
    };
    CUtensorMap tmX  = mkmap(pxp, 4096);
    CUtensorMap tmWq = mkmap(pwq, 6144);
    CUtensorMap tmAt = mkmap(pat, 4096);
    CUtensorMap tmWo = mkmap(pwo, 2048);

    cudaFuncSetAttribute(mma_gemm_kernel<0>,
                         cudaFuncAttributeMaxDynamicSharedMemorySize, GEMM_DSMEM);
    cudaFuncSetAttribute(mma_gemm_kernel<1>,
                         cudaFuncAttributeMaxDynamicSharedMemorySize, GEMM_DSMEM);
    cudaFuncSetAttribute(flash_kernel,
                         cudaFuncAttributeMaxDynamicSharedMemorySize, FLASH_SMEM);

    // pack inputs to bf16 hi/lo split
    pack_kernel<<<8192, 256>>>(x, 0, 2);        // g_xp    [hi|hi|lo]
    pack_kernel<<<12288, 256>>>(w_qkv, 1, 1);   // g_wqkvp [hi|lo|hi]
    pack_kernel<<<4096, 256>>>(w_out, 2, 1);    // g_woutp [hi|lo|hi]

    // QKV projection on tensor cores (M=4096, N=6144)
    mma_gemm_kernel<0><<<dim3(48, 32), 256, GEMM_DSMEM>>>(tmX, tmWq, b_qkv, nullptr);

    rope_kernel<<<(NB * NH * NT * HALF) / 256, 256>>>();
    flash_kernel<<<dim3(32, 32), 256, FLASH_SMEM>>>();

    // pack attention output, then out-projection (M=4096, N=2048)
    pack_kernel<<<8192, 256>>>(nullptr, 3, 2);  // g_attnp [hi|hi|lo]
    mma_gemm_kernel<1><<<dim3(16, 32), 256, GEMM_DSMEM>>>(tmAt, tmWo, b_out, out);
}